// round 13
// baseline (speedup 1.0000x reference)
#include <cuda_runtime.h>
#include <math_constants.h>
#include <cstdint>

#define NNODES 65536
#define NEDGES 1048576
#define NGRAPH 64
#define NPER   1024
#define FEAT   64
#define HID    128
#define TOPK   10
#define EPG    16384   // edges per graph (exact: NPER * DEG)

// ---------------- device scratch (no allocations allowed) ----------------
__device__ int    g_deg[NNODES];
__device__ float  g_dinv[NNODES];
__device__ int    g_off[NNODES];
__device__ int    g_cursor[NNODES];
__device__ float2 g_csre[NEDGES];   // {bits(src global), norm}
__device__ float  g_c[NNODES];
__device__ float  g_T0[NNODES * HID];
__device__ float  g_T1[NNODES * HID];
__device__ float  g_mpp[NGRAPH * 8 * HID];
__device__ float  g_gW[NGRAPH * HID];
__device__ float  g_z[NNODES];

// ---------------- tf32 helpers ----------------
__device__ __forceinline__ void split_tf32(float a, uint32_t& hi, uint32_t& lo) {
    asm("cvt.rna.tf32.f32 %0, %1;" : "=r"(hi) : "f"(a));
    float r = a - __uint_as_float(hi);
    asm("cvt.rna.tf32.f32 %0, %1;" : "=r"(lo) : "f"(r));
}

__device__ __forceinline__ void mma_tf32(float4& d, const uint32_t a[4], const uint32_t b[2]) {
    asm volatile(
        "mma.sync.aligned.m16n8k8.row.col.f32.tf32.tf32.f32 "
        "{%0,%1,%2,%3}, {%4,%5,%6,%7}, {%8,%9}, {%0,%1,%2,%3};"
        : "+f"(d.x), "+f"(d.y), "+f"(d.z), "+f"(d.w)
        : "r"(a[0]), "r"(a[1]), "r"(a[2]), "r"(a[3]), "r"(b[0]), "r"(b[1]));
}

// ---------------- CSR construction ----------------
__global__ void k_hist(const int* __restrict__ edst) {
    int e = blockIdx.x * 256 + threadIdx.x;
    if (e < NEDGES) atomicAdd(&g_deg[edst[e]], 1);
}

// per-graph scan: block = graph (1024 threads). Cross-graph base is the exact
// constant g*EPG. Fuses dinv.
__global__ __launch_bounds__(1024) void k_scan() {
    __shared__ int wsum[32];
    const int g = blockIdx.x, t = threadIdx.x;
    const int lane = t & 31, w = t >> 5;
    const int i = g * NPER + t;
    const int v = g_deg[i];
    g_dinv[i] = rsqrtf((float)(v + 1));
    int x = v;
    #pragma unroll
    for (int o = 1; o < 32; o <<= 1) {
        int y = __shfl_up_sync(0xffffffffu, x, o);
        if (lane >= o) x += y;
    }
    if (lane == 31) wsum[w] = x;
    __syncthreads();
    if (w == 0) {
        int s = wsum[lane];
        #pragma unroll
        for (int o = 1; o < 32; o <<= 1) {
            int y = __shfl_up_sync(0xffffffffu, s, o);
            if (lane >= o) s += y;
        }
        wsum[lane] = s;
    }
    __syncthreads();
    int off = g * EPG + (w ? wsum[w - 1] : 0) + x - v;   // exclusive
    g_off[i] = off;
    g_cursor[i] = off;
}

__global__ void k_fill(const int* __restrict__ esrc, const int* __restrict__ edst) {
    int e = blockIdx.x * 256 + threadIdx.x;
    if (e >= NEDGES) return;
    int s = esrc[e], d = edst[e];
    float nr = g_dinv[s] * g_dinv[d];
    int slot = atomicAdd(&g_cursor[d], 1);
    g_csre[slot] = make_float2(__int_as_float(s), nr);
}

// ---------------- sparse aggregations (warp per node, packed CSR, unroll-8) -------
template <bool WRITE_C>
__global__ __launch_bounds__(256) void k_agg64(const float* __restrict__ X,
                                               float* __restrict__ Y) {
    int node = blockIdx.x * 8 + (threadIdx.x >> 5);
    int lane = threadIdx.x & 31;
    const float2* xs = (const float2*)X;
    float dv = g_dinv[node];
    float2 xv = xs[node * 32 + lane];
    float2 acc;
    acc.x = dv * dv * xv.x;
    acc.y = dv * dv * xv.y;
    float csum = dv * dv;
    const int jb = g_off[node], deg = g_deg[node];
    const float2* ep = &g_csre[jb];
    int j = deg & 7;
    for (int jj = 0; jj < j; jj++) {
        float2 e = ep[jj];
        float2 v = xs[__float_as_int(e.x) * 32 + lane];
        acc.x += e.y * v.x;
        acc.y += e.y * v.y;
        if (WRITE_C) csum += e.y;
    }
    for (; j < deg; j += 8) {
        float2 e0 = ep[j],     e1 = ep[j + 1], e2 = ep[j + 2], e3 = ep[j + 3];
        float2 e4 = ep[j + 4], e5 = ep[j + 5], e6 = ep[j + 6], e7 = ep[j + 7];
        float2 v0 = xs[__float_as_int(e0.x) * 32 + lane];
        float2 v1 = xs[__float_as_int(e1.x) * 32 + lane];
        float2 v2 = xs[__float_as_int(e2.x) * 32 + lane];
        float2 v3 = xs[__float_as_int(e3.x) * 32 + lane];
        float2 v4 = xs[__float_as_int(e4.x) * 32 + lane];
        float2 v5 = xs[__float_as_int(e5.x) * 32 + lane];
        float2 v6 = xs[__float_as_int(e6.x) * 32 + lane];
        float2 v7 = xs[__float_as_int(e7.x) * 32 + lane];
        acc.x += e0.y * v0.x; acc.y += e0.y * v0.y;
        acc.x += e1.y * v1.x; acc.y += e1.y * v1.y;
        acc.x += e2.y * v2.x; acc.y += e2.y * v2.y;
        acc.x += e3.y * v3.x; acc.y += e3.y * v3.y;
        acc.x += e4.y * v4.x; acc.y += e4.y * v4.y;
        acc.x += e5.y * v5.x; acc.y += e5.y * v5.y;
        acc.x += e6.y * v6.x; acc.y += e6.y * v6.y;
        acc.x += e7.y * v7.x; acc.y += e7.y * v7.y;
        if (WRITE_C) csum += e0.y + e1.y + e2.y + e3.y + e4.y + e5.y + e6.y + e7.y;
    }
    ((float2*)Y)[node * 32 + lane] = acc;
    if (WRITE_C && lane == 0) g_c[node] = csum;
}

__global__ __launch_bounds__(256) void k_agg128(const float* __restrict__ X,
                                                float* __restrict__ Y) {
    int node = blockIdx.x * 8 + (threadIdx.x >> 5);
    int lane = threadIdx.x & 31;
    const float4* xs = (const float4*)X;
    float dv = g_dinv[node];
    float4 xv = xs[node * 32 + lane];
    float4 acc;
    float sl = dv * dv;
    acc.x = sl * xv.x; acc.y = sl * xv.y; acc.z = sl * xv.z; acc.w = sl * xv.w;
    const int jb = g_off[node], deg = g_deg[node];
    const float2* ep = &g_csre[jb];
    int j = deg & 7;
    for (int jj = 0; jj < j; jj++) {
        float2 e = ep[jj];
        float4 v = xs[__float_as_int(e.x) * 32 + lane];
        acc.x += e.y * v.x; acc.y += e.y * v.y; acc.z += e.y * v.z; acc.w += e.y * v.w;
    }
    for (; j < deg; j += 8) {
        float2 e0 = ep[j],     e1 = ep[j + 1], e2 = ep[j + 2], e3 = ep[j + 3];
        float2 e4 = ep[j + 4], e5 = ep[j + 5], e6 = ep[j + 6], e7 = ep[j + 7];
        float4 v0 = xs[__float_as_int(e0.x) * 32 + lane];
        float4 v1 = xs[__float_as_int(e1.x) * 32 + lane];
        float4 v2 = xs[__float_as_int(e2.x) * 32 + lane];
        float4 v3 = xs[__float_as_int(e3.x) * 32 + lane];
        float4 v4 = xs[__float_as_int(e4.x) * 32 + lane];
        float4 v5 = xs[__float_as_int(e5.x) * 32 + lane];
        float4 v6 = xs[__float_as_int(e6.x) * 32 + lane];
        float4 v7 = xs[__float_as_int(e7.x) * 32 + lane];
        acc.x += e0.y * v0.x; acc.y += e0.y * v0.y; acc.z += e0.y * v0.z; acc.w += e0.y * v0.w;
        acc.x += e1.y * v1.x; acc.y += e1.y * v1.y; acc.z += e1.y * v1.z; acc.w += e1.y * v1.w;
        acc.x += e2.y * v2.x; acc.y += e2.y * v2.y; acc.z += e2.y * v2.z; acc.w += e2.y * v2.w;
        acc.x += e3.y * v3.x; acc.y += e3.y * v3.y; acc.z += e3.y * v3.z; acc.w += e3.y * v3.w;
        acc.x += e4.y * v4.x; acc.y += e4.y * v4.y; acc.z += e4.y * v4.z; acc.w += e4.y * v4.w;
        acc.x += e5.y * v5.x; acc.y += e5.y * v5.y; acc.z += e5.y * v5.z; acc.w += e5.y * v5.w;
        acc.x += e6.y * v6.x; acc.y += e6.y * v6.y; acc.z += e6.y * v6.z; acc.w += e6.y * v6.w;
        acc.x += e7.y * v7.x; acc.y += e7.y * v7.y; acc.z += e7.y * v7.z; acc.w += e7.y * v7.w;
    }
    ((float4*)Y)[node * 32 + lane] = acc;
}

// ---------------- 3xTF32 mma.sync GEMM: per-block 128 rows x 128 cols --------------
// B is tf32-split ONCE at smem staging (sBh/sBl); mainloop B is pure LDS.
// MAXP: fold maxpool stage-1 into epilogue. ZOUT: skip Y store, emit z = h . W3.
template <int K, bool RELU, bool GLOB, bool MAXP, bool ZOUT>
__global__ __launch_bounds__(256) void k_mgemm(
    const float* __restrict__ A, const float* __restrict__ W,
    const float* __restrict__ bias, float* __restrict__ Y,
    const float* __restrict__ W3) {
    extern __shared__ float sm[];
    __shared__ int   smax[128];
    __shared__ float szp[128][8];
    const int PA = K + 4;
    float* sA  = sm;                      // 128 * PA (fp32)
    float* sBh = sm + 128 * PA;           // K * 136 (tf32 hi)
    float* sBl = sBh + K * 136;           // K * 136 (tf32 lo residual)
    const int tid = threadIdx.x;
    const int rbase = blockIdx.x * 128;

    if (MAXP && tid < 128) smax[tid] = 0;

    for (int i = tid; i < 128 * (K / 4); i += 256) {
        int row = i / (K / 4), c = i % (K / 4);
        float4 v = *(const float4*)&A[(size_t)(rbase + row) * K + c * 4];
        *(float4*)&sA[row * PA + c * 4] = v;
    }
    for (int i = tid; i < K * 128; i += 256) {
        int row = i >> 7, c = i & 127;
        uint32_t hi, lo;
        split_tf32(W[i], hi, lo);
        sBh[row * 136 + c] = __uint_as_float(hi);
        sBl[row * 136 + c] = __uint_as_float(lo);
    }
    __syncthreads();

    const int lane = tid & 31, wid = tid >> 5;
    const int gp = lane >> 2, tg = lane & 3;
    const int m0 = (wid & 3) * 32, n0 = (wid >> 2) * 64;

    float4 acc[2][8];
    #pragma unroll
    for (int mf = 0; mf < 2; mf++)
        #pragma unroll
        for (int f = 0; f < 8; f++) acc[mf][f] = make_float4(0.f, 0.f, 0.f, 0.f);

    for (int ks = 0; ks < K / 8; ks++) {
        const int kc = ks * 8;
        uint32_t ah[2][4], al[2][4];
        #pragma unroll
        for (int mf = 0; mf < 2; mf++) {
            int r0 = m0 + mf * 16 + gp;
            float x0 = sA[r0 * PA + kc + tg];
            float x1 = sA[(r0 + 8) * PA + kc + tg];
            float x2 = sA[r0 * PA + kc + tg + 4];
            float x3 = sA[(r0 + 8) * PA + kc + tg + 4];
            split_tf32(x0, ah[mf][0], al[mf][0]);
            split_tf32(x1, ah[mf][1], al[mf][1]);
            split_tf32(x2, ah[mf][2], al[mf][2]);
            split_tf32(x3, ah[mf][3], al[mf][3]);
        }
        #pragma unroll
        for (int f = 0; f < 8; f++) {
            int n = n0 + f * 8 + gp;
            uint32_t bh[2], bl[2];
            bh[0] = __float_as_uint(sBh[(kc + tg) * 136 + n]);
            bh[1] = __float_as_uint(sBh[(kc + tg + 4) * 136 + n]);
            bl[0] = __float_as_uint(sBl[(kc + tg) * 136 + n]);
            bl[1] = __float_as_uint(sBl[(kc + tg + 4) * 136 + n]);
            #pragma unroll
            for (int mf = 0; mf < 2; mf++) {
                mma_tf32(acc[mf][f], ah[mf], bh);
                mma_tf32(acc[mf][f], ah[mf], bl);
                mma_tf32(acc[mf][f], al[mf], bh);
            }
        }
    }

    float colmax[8][2];
    if (MAXP) {
        #pragma unroll
        for (int f = 0; f < 8; f++) { colmax[f][0] = 0.f; colmax[f][1] = 0.f; }
    }
    float zp[2][2] = {{0.f, 0.f}, {0.f, 0.f}};

    const float* gw = GLOB ? &g_gW[(rbase >> 10) * HID] : nullptr;
    #pragma unroll
    for (int mf = 0; mf < 2; mf++) {
        int r0 = rbase + m0 + mf * 16 + gp;
        int r1 = r0 + 8;
        float cc0 = GLOB ? g_c[r0] : 0.f;
        float cc1 = GLOB ? g_c[r1] : 0.f;
        #pragma unroll
        for (int f = 0; f < 8; f++) {
            int c = n0 + f * 8 + 2 * tg;
            float2 bv = *(const float2*)&bias[c];
            float4 a = acc[mf][f];
            float2 o0 = {a.x + bv.x, a.y + bv.y};
            float2 o1 = {a.z + bv.x, a.w + bv.y};
            if (GLOB) {
                float2 gv = *(const float2*)&gw[c];
                o0.x += cc0 * gv.x; o0.y += cc0 * gv.y;
                o1.x += cc1 * gv.x; o1.y += cc1 * gv.y;
            }
            if (RELU) {
                o0.x = fmaxf(o0.x, 0.f); o0.y = fmaxf(o0.y, 0.f);
                o1.x = fmaxf(o1.x, 0.f); o1.y = fmaxf(o1.y, 0.f);
            }
            if (!ZOUT) {
                *(float2*)&Y[(size_t)r0 * 128 + c] = o0;
                *(float2*)&Y[(size_t)r1 * 128 + c] = o1;
            }
            if (MAXP) {
                colmax[f][0] = fmaxf(colmax[f][0], fmaxf(o0.x, o1.x));
                colmax[f][1] = fmaxf(colmax[f][1], fmaxf(o0.y, o1.y));
            }
            if (ZOUT) {
                float w3a = W3[c], w3b = W3[c + 1];
                zp[mf][0] += o0.x * w3a + o0.y * w3b;
                zp[mf][1] += o1.x * w3a + o1.y * w3b;
            }
        }
    }

    if (MAXP) {
        #pragma unroll
        for (int f = 0; f < 8; f++) {
            int c = n0 + f * 8 + 2 * tg;
            atomicMax(&smax[c],     __float_as_int(colmax[f][0]));
            atomicMax(&smax[c + 1], __float_as_int(colmax[f][1]));
        }
        __syncthreads();
        if (tid < 128) g_mpp[(size_t)blockIdx.x * HID + tid] = __int_as_float(smax[tid]);
    }

    if (ZOUT) {
        int slot = ((wid >> 2) << 2) | tg;
        #pragma unroll
        for (int mf = 0; mf < 2; mf++) {
            szp[m0 + mf * 16 + gp][slot]     = zp[mf][0];
            szp[m0 + mf * 16 + gp + 8][slot] = zp[mf][1];
        }
        __syncthreads();
        if (tid < 128) {
            float z = 0.f;
            #pragma unroll
            for (int k = 0; k < 8; k++) z += szp[tid][k];
            g_z[rbase + tid] = z;
        }
    }
}

// ---------------- fused maxpool stage-2 + global path matmuls ----------------
__global__ void k_globs2(const float* __restrict__ Wf, const float* __restrict__ bf,
                         const float* __restrict__ W2) {
    __shared__ float s1[HID];
    __shared__ float s2[HID];
    int g = blockIdx.x, t = threadIdx.x;
    float m = -CUDART_INF_F;
    #pragma unroll
    for (int s = 0; s < 8; s++) m = fmaxf(m, g_mpp[(g * 8 + s) * HID + t]);
    s1[t] = m;
    __syncthreads();
    float acc = bf[t];
    for (int k = 0; k < HID; k++) acc += s1[k] * Wf[k * HID + t];
    s2[t] = acc;
    __syncthreads();
    float a2 = 0.f;
    for (int k = 0; k < HID; k++) a2 += s2[k] * W2[(HID + k) * HID + t];
    g_gW[g * HID + t] = a2;
}

// ---------------- fused logit + per-graph top-K mask ----------------
// z staged in smem; src indices masked to graph-local (edges are intra-graph).
__global__ __launch_bounds__(256) void k_logitk(const float* __restrict__ b3,
                                                float* __restrict__ out) {
    __shared__ float sz[NPER];
    __shared__ float slog[NPER];
    __shared__ float v[NPER];
    __shared__ float wmax[8];
    __shared__ float sth;
    __shared__ int sidx;
    const int g = blockIdx.x, t = threadIdx.x;
    const int lane = t & 31, warp = t >> 5;
    const float bb = b3[0];

    for (int i = t; i < NPER; i += 256) sz[i] = g_z[g * NPER + i];
    __syncthreads();

    for (int ln = warp; ln < NPER; ln += 8) {
        int node = g * NPER + ln;
        int jb = g_off[node], dg = g_deg[node];
        float part = 0.f;
        for (int j = lane; j < dg; j += 32) {
            float2 e = g_csre[jb + j];
            part += e.y * sz[__float_as_int(e.x) & (NPER - 1)];
        }
        #pragma unroll
        for (int o = 16; o; o >>= 1) part += __shfl_xor_sync(0xffffffffu, part, o);
        if (lane == 0) {
            float dv = g_dinv[node];
            float lv = part + dv * dv * sz[ln] + bb;
            slog[ln] = lv;
            v[ln] = lv;
        }
    }
    __syncthreads();

    for (int it = 0; it < TOPK; it++) {
        float m = -CUDART_INF_F;
        for (int i = t; i < NPER; i += 256) m = fmaxf(m, v[i]);
        #pragma unroll
        for (int o = 16; o; o >>= 1) m = fmaxf(m, __shfl_xor_sync(0xffffffffu, m, o));
        if (lane == 0) wmax[warp] = m;
        __syncthreads();
        if (t == 0) {
            float mm = wmax[0];
            #pragma unroll
            for (int w = 1; w < 8; w++) mm = fmaxf(mm, wmax[w]);
            sth = mm;
            sidx = 0x7fffffff;
        }
        __syncthreads();
        float mm = sth;
        for (int i = t; i < NPER; i += 256)
            if (v[i] == mm) atomicMin(&sidx, i);
        __syncthreads();
        if (t == 0) v[sidx] = -CUDART_INF_F;
        __syncthreads();
    }
    float th = sth;
    for (int i = t; i < NPER; i += 256)
        out[g * NPER + i] = (slog[i] >= th) ? 1.0f : 0.0f;
}

// ---------------- host launcher ----------------
extern "C" void kernel_launch(void* const* d_in, const int* in_sizes, int n_in,
                              void* d_out, int out_size) {
    const float* x    = (const float*)d_in[0];
    const int*   esrc = (const int*)d_in[1];
    const int*   edst = (const int*)d_in[2];
    const float* W0 = (const float*)d_in[4];
    const float* b0 = (const float*)d_in[5];
    const float* W1 = (const float*)d_in[6];
    const float* b1 = (const float*)d_in[7];
    const float* Wf = (const float*)d_in[8];
    const float* bf = (const float*)d_in[9];
    const float* W2 = (const float*)d_in[10];
    const float* b2 = (const float*)d_in[11];
    const float* W3 = (const float*)d_in[12];
    const float* b3 = (const float*)d_in[13];
    float* out = (float*)d_out;

    float *T0, *T1;
    int* degp;
    cudaGetSymbolAddress((void**)&T0, g_T0);
    cudaGetSymbolAddress((void**)&T1, g_T1);
    cudaGetSymbolAddress((void**)&degp, g_deg);

    const int SM64  = (128 * 68  + 2 * 64  * 136) * 4;   // 104448
    const int SM128 = (128 * 132 + 2 * 128 * 136) * 4;   // 206848
    cudaFuncSetAttribute(k_mgemm<64, true, false, true, false>,
                         cudaFuncAttributeMaxDynamicSharedMemorySize, SM64);
    cudaFuncSetAttribute(k_mgemm<128, true, false, false, false>,
                         cudaFuncAttributeMaxDynamicSharedMemorySize, SM128);
    cudaFuncSetAttribute(k_mgemm<128, true, true, false, true>,
                         cudaFuncAttributeMaxDynamicSharedMemorySize, SM128);

    // --- CSR + norms (hist -> fused per-graph scan -> fill) ---
    cudaMemsetAsync(degp, 0, NNODES * sizeof(int));
    k_hist<<<NEDGES / 256, 256>>>(edst);
    k_scan<<<NGRAPH, 1024>>>();
    k_fill<<<NEDGES / 256, 256>>>(esrc, edst);

    // --- conv0: h0 = relu(agg(x) @ W0 + b0); epilogue emits maxpool partials ---
    k_agg64<true><<<NNODES / 8, 256>>>(x, T1);
    k_mgemm<64, true, false, true, false><<<NNODES / 128, 256, SM64>>>(T1, W0, b0, T0, nullptr);

    // --- global path: mp2 + (mp @ Wf + bf) @ W2_bottom ---
    k_globs2<<<NGRAPH, HID>>>(Wf, bf, W2);

    // --- conv1 (applied twice with same weights) ---
    k_agg128<<<NNODES / 8, 256>>>(T0, T1);
    k_mgemm<128, true, false, false, false><<<NNODES / 128, 256, SM128>>>(T1, W1, b1, T0, nullptr);
    k_agg128<<<NNODES / 8, 256>>>(T0, T1);
    k_mgemm<128, true, false, false, false><<<NNODES / 128, 256, SM128>>>(T1, W1, b1, T0, nullptr);

    // --- conv2 + conv3 projection fused: epilogue computes z = h . W3, no h store ---
    k_agg128<<<NNODES / 8, 256>>>(T0, T1);
    k_mgemm<128, true, true, false, true><<<NNODES / 128, 256, SM128>>>(T1, W2, b2, nullptr, W3);

    // --- fused logit + per-graph top-10 mask ---
    k_logitk<<<NGRAPH, 256>>>(b3, out);
}

// round 14
// speedup vs baseline: 1.0048x; 1.0048x over previous
#include <cuda_runtime.h>
#include <math_constants.h>
#include <cstdint>

#define NNODES 65536
#define NEDGES 1048576
#define NGRAPH 64
#define NPER   1024
#define FEAT   64
#define HID    128
#define TOPK   10
#define EPG    16384   // edges per graph (exact: NPER * DEG)

// ---------------- device scratch (no allocations allowed) ----------------
__device__ int    g_deg[NNODES];
__device__ float  g_dinv[NNODES];
__device__ int    g_off[NNODES];
__device__ int    g_cursor[NNODES];
__device__ float2 g_csre[NEDGES];   // {bits(src global), norm}
__device__ float  g_c[NNODES];
__device__ float  g_T0[NNODES * HID];
__device__ float  g_T1[NNODES * HID];
__device__ float  g_mpp[NGRAPH * 8 * HID];
__device__ float  g_gW[NGRAPH * HID];
__device__ float  g_z[NNODES];

// ---------------- tf32 helpers ----------------
__device__ __forceinline__ void split_tf32(float a, uint32_t& hi, uint32_t& lo) {
    asm("cvt.rna.tf32.f32 %0, %1;" : "=r"(hi) : "f"(a));
    float r = a - __uint_as_float(hi);
    asm("cvt.rna.tf32.f32 %0, %1;" : "=r"(lo) : "f"(r));
}

__device__ __forceinline__ void mma_tf32(float4& d, const uint32_t a[4], const uint32_t b[2]) {
    asm volatile(
        "mma.sync.aligned.m16n8k8.row.col.f32.tf32.tf32.f32 "
        "{%0,%1,%2,%3}, {%4,%5,%6,%7}, {%8,%9}, {%0,%1,%2,%3};"
        : "+f"(d.x), "+f"(d.y), "+f"(d.z), "+f"(d.w)
        : "r"(a[0]), "r"(a[1]), "r"(a[2]), "r"(a[3]), "r"(b[0]), "r"(b[1]));
}

// ---------------- CSR construction ----------------
__global__ void k_hist(const int* __restrict__ edst) {
    int e = blockIdx.x * 256 + threadIdx.x;
    if (e < NEDGES) atomicAdd(&g_deg[edst[e]], 1);
}

// per-graph scan: block = graph (1024 threads). Cross-graph base is the exact
// constant g*EPG. Fuses dinv.
__global__ __launch_bounds__(1024) void k_scan() {
    __shared__ int wsum[32];
    const int g = blockIdx.x, t = threadIdx.x;
    const int lane = t & 31, w = t >> 5;
    const int i = g * NPER + t;
    const int v = g_deg[i];
    g_dinv[i] = rsqrtf((float)(v + 1));
    int x = v;
    #pragma unroll
    for (int o = 1; o < 32; o <<= 1) {
        int y = __shfl_up_sync(0xffffffffu, x, o);
        if (lane >= o) x += y;
    }
    if (lane == 31) wsum[w] = x;
    __syncthreads();
    if (w == 0) {
        int s = wsum[lane];
        #pragma unroll
        for (int o = 1; o < 32; o <<= 1) {
            int y = __shfl_up_sync(0xffffffffu, s, o);
            if (lane >= o) s += y;
        }
        wsum[lane] = s;
    }
    __syncthreads();
    int off = g * EPG + (w ? wsum[w - 1] : 0) + x - v;   // exclusive
    g_off[i] = off;
    g_cursor[i] = off;
}

__global__ void k_fill(const int* __restrict__ esrc, const int* __restrict__ edst) {
    int e = blockIdx.x * 256 + threadIdx.x;
    if (e >= NEDGES) return;
    int s = esrc[e], d = edst[e];
    float nr = g_dinv[s] * g_dinv[d];
    int slot = atomicAdd(&g_cursor[d], 1);
    g_csre[slot] = make_float2(__int_as_float(s), nr);
}

// ---------------- sparse aggregations (warp per node, packed CSR, unroll-8) -------
template <bool WRITE_C>
__global__ __launch_bounds__(256) void k_agg64(const float* __restrict__ X,
                                               float* __restrict__ Y) {
    int node = blockIdx.x * 8 + (threadIdx.x >> 5);
    int lane = threadIdx.x & 31;
    const float2* xs = (const float2*)X;
    float dv = g_dinv[node];
    float2 xv = xs[node * 32 + lane];
    float2 acc;
    acc.x = dv * dv * xv.x;
    acc.y = dv * dv * xv.y;
    float csum = dv * dv;
    const int jb = g_off[node], deg = g_deg[node];
    const float2* ep = &g_csre[jb];
    int j = deg & 7;
    for (int jj = 0; jj < j; jj++) {
        float2 e = ep[jj];
        float2 v = xs[__float_as_int(e.x) * 32 + lane];
        acc.x += e.y * v.x;
        acc.y += e.y * v.y;
        if (WRITE_C) csum += e.y;
    }
    for (; j < deg; j += 8) {
        float2 e0 = ep[j],     e1 = ep[j + 1], e2 = ep[j + 2], e3 = ep[j + 3];
        float2 e4 = ep[j + 4], e5 = ep[j + 5], e6 = ep[j + 6], e7 = ep[j + 7];
        float2 v0 = xs[__float_as_int(e0.x) * 32 + lane];
        float2 v1 = xs[__float_as_int(e1.x) * 32 + lane];
        float2 v2 = xs[__float_as_int(e2.x) * 32 + lane];
        float2 v3 = xs[__float_as_int(e3.x) * 32 + lane];
        float2 v4 = xs[__float_as_int(e4.x) * 32 + lane];
        float2 v5 = xs[__float_as_int(e5.x) * 32 + lane];
        float2 v6 = xs[__float_as_int(e6.x) * 32 + lane];
        float2 v7 = xs[__float_as_int(e7.x) * 32 + lane];
        acc.x += e0.y * v0.x; acc.y += e0.y * v0.y;
        acc.x += e1.y * v1.x; acc.y += e1.y * v1.y;
        acc.x += e2.y * v2.x; acc.y += e2.y * v2.y;
        acc.x += e3.y * v3.x; acc.y += e3.y * v3.y;
        acc.x += e4.y * v4.x; acc.y += e4.y * v4.y;
        acc.x += e5.y * v5.x; acc.y += e5.y * v5.y;
        acc.x += e6.y * v6.x; acc.y += e6.y * v6.y;
        acc.x += e7.y * v7.x; acc.y += e7.y * v7.y;
        if (WRITE_C) csum += e0.y + e1.y + e2.y + e3.y + e4.y + e5.y + e6.y + e7.y;
    }
    ((float2*)Y)[node * 32 + lane] = acc;
    if (WRITE_C && lane == 0) g_c[node] = csum;
}

__global__ __launch_bounds__(256) void k_agg128(const float* __restrict__ X,
                                                float* __restrict__ Y) {
    int node = blockIdx.x * 8 + (threadIdx.x >> 5);
    int lane = threadIdx.x & 31;
    const float4* xs = (const float4*)X;
    float dv = g_dinv[node];
    float4 xv = xs[node * 32 + lane];
    float4 acc;
    float sl = dv * dv;
    acc.x = sl * xv.x; acc.y = sl * xv.y; acc.z = sl * xv.z; acc.w = sl * xv.w;
    const int jb = g_off[node], deg = g_deg[node];
    const float2* ep = &g_csre[jb];
    int j = deg & 7;
    for (int jj = 0; jj < j; jj++) {
        float2 e = ep[jj];
        float4 v = xs[__float_as_int(e.x) * 32 + lane];
        acc.x += e.y * v.x; acc.y += e.y * v.y; acc.z += e.y * v.z; acc.w += e.y * v.w;
    }
    for (; j < deg; j += 8) {
        float2 e0 = ep[j],     e1 = ep[j + 1], e2 = ep[j + 2], e3 = ep[j + 3];
        float2 e4 = ep[j + 4], e5 = ep[j + 5], e6 = ep[j + 6], e7 = ep[j + 7];
        float4 v0 = xs[__float_as_int(e0.x) * 32 + lane];
        float4 v1 = xs[__float_as_int(e1.x) * 32 + lane];
        float4 v2 = xs[__float_as_int(e2.x) * 32 + lane];
        float4 v3 = xs[__float_as_int(e3.x) * 32 + lane];
        float4 v4 = xs[__float_as_int(e4.x) * 32 + lane];
        float4 v5 = xs[__float_as_int(e5.x) * 32 + lane];
        float4 v6 = xs[__float_as_int(e6.x) * 32 + lane];
        float4 v7 = xs[__float_as_int(e7.x) * 32 + lane];
        acc.x += e0.y * v0.x; acc.y += e0.y * v0.y; acc.z += e0.y * v0.z; acc.w += e0.y * v0.w;
        acc.x += e1.y * v1.x; acc.y += e1.y * v1.y; acc.z += e1.y * v1.z; acc.w += e1.y * v1.w;
        acc.x += e2.y * v2.x; acc.y += e2.y * v2.y; acc.z += e2.y * v2.z; acc.w += e2.y * v2.w;
        acc.x += e3.y * v3.x; acc.y += e3.y * v3.y; acc.z += e3.y * v3.z; acc.w += e3.y * v3.w;
        acc.x += e4.y * v4.x; acc.y += e4.y * v4.y; acc.z += e4.y * v4.z; acc.w += e4.y * v4.w;
        acc.x += e5.y * v5.x; acc.y += e5.y * v5.y; acc.z += e5.y * v5.z; acc.w += e5.y * v5.w;
        acc.x += e6.y * v6.x; acc.y += e6.y * v6.y; acc.z += e6.y * v6.z; acc.w += e6.y * v6.w;
        acc.x += e7.y * v7.x; acc.y += e7.y * v7.y; acc.z += e7.y * v7.z; acc.w += e7.y * v7.w;
    }
    ((float4*)Y)[node * 32 + lane] = acc;
}

// ---------------- 3xTF32 mma.sync GEMM: per-block 128 rows x 128 cols --------------
// B is tf32-split ONCE at smem staging (sBh/sBl); mainloop B is pure LDS.
// MAXP: fold maxpool stage-1 into epilogue. ZOUT: skip Y store, emit z = h . W3.
template <int K, bool RELU, bool GLOB, bool MAXP, bool ZOUT>
__global__ __launch_bounds__(256) void k_mgemm(
    const float* __restrict__ A, const float* __restrict__ W,
    const float* __restrict__ bias, float* __restrict__ Y,
    const float* __restrict__ W3) {
    extern __shared__ float sm[];
    __shared__ int   smax[128];
    __shared__ float szp[128][8];
    const int PA = K + 4;
    float* sA  = sm;                      // 128 * PA (fp32)
    float* sBh = sm + 128 * PA;           // K * 136 (tf32 hi)
    float* sBl = sBh + K * 136;           // K * 136 (tf32 lo residual)
    const int tid = threadIdx.x;
    const int rbase = blockIdx.x * 128;

    if (MAXP && tid < 128) smax[tid] = 0;

    for (int i = tid; i < 128 * (K / 4); i += 256) {
        int row = i / (K / 4), c = i % (K / 4);
        float4 v = *(const float4*)&A[(size_t)(rbase + row) * K + c * 4];
        *(float4*)&sA[row * PA + c * 4] = v;
    }
    for (int i = tid; i < K * 128; i += 256) {
        int row = i >> 7, c = i & 127;
        uint32_t hi, lo;
        split_tf32(W[i], hi, lo);
        sBh[row * 136 + c] = __uint_as_float(hi);
        sBl[row * 136 + c] = __uint_as_float(lo);
    }
    __syncthreads();

    const int lane = tid & 31, wid = tid >> 5;
    const int gp = lane >> 2, tg = lane & 3;
    const int m0 = (wid & 3) * 32, n0 = (wid >> 2) * 64;

    float4 acc[2][8];
    #pragma unroll
    for (int mf = 0; mf < 2; mf++)
        #pragma unroll
        for (int f = 0; f < 8; f++) acc[mf][f] = make_float4(0.f, 0.f, 0.f, 0.f);

    for (int ks = 0; ks < K / 8; ks++) {
        const int kc = ks * 8;
        uint32_t ah[2][4], al[2][4];
        #pragma unroll
        for (int mf = 0; mf < 2; mf++) {
            int r0 = m0 + mf * 16 + gp;
            float x0 = sA[r0 * PA + kc + tg];
            float x1 = sA[(r0 + 8) * PA + kc + tg];
            float x2 = sA[r0 * PA + kc + tg + 4];
            float x3 = sA[(r0 + 8) * PA + kc + tg + 4];
            split_tf32(x0, ah[mf][0], al[mf][0]);
            split_tf32(x1, ah[mf][1], al[mf][1]);
            split_tf32(x2, ah[mf][2], al[mf][2]);
            split_tf32(x3, ah[mf][3], al[mf][3]);
        }
        #pragma unroll
        for (int f = 0; f < 8; f++) {
            int n = n0 + f * 8 + gp;
            uint32_t bh[2], bl[2];
            bh[0] = __float_as_uint(sBh[(kc + tg) * 136 + n]);
            bh[1] = __float_as_uint(sBh[(kc + tg + 4) * 136 + n]);
            bl[0] = __float_as_uint(sBl[(kc + tg) * 136 + n]);
            bl[1] = __float_as_uint(sBl[(kc + tg + 4) * 136 + n]);
            #pragma unroll
            for (int mf = 0; mf < 2; mf++) {
                mma_tf32(acc[mf][f], ah[mf], bh);
                mma_tf32(acc[mf][f], ah[mf], bl);
                mma_tf32(acc[mf][f], al[mf], bh);
            }
        }
    }

    float colmax[8][2];
    if (MAXP) {
        #pragma unroll
        for (int f = 0; f < 8; f++) { colmax[f][0] = 0.f; colmax[f][1] = 0.f; }
    }
    float zp[2][2] = {{0.f, 0.f}, {0.f, 0.f}};

    const float* gw = GLOB ? &g_gW[(rbase >> 10) * HID] : nullptr;
    #pragma unroll
    for (int mf = 0; mf < 2; mf++) {
        int r0 = rbase + m0 + mf * 16 + gp;
        int r1 = r0 + 8;
        float cc0 = GLOB ? g_c[r0] : 0.f;
        float cc1 = GLOB ? g_c[r1] : 0.f;
        #pragma unroll
        for (int f = 0; f < 8; f++) {
            int c = n0 + f * 8 + 2 * tg;
            float2 bv = *(const float2*)&bias[c];
            float4 a = acc[mf][f];
            float2 o0 = {a.x + bv.x, a.y + bv.y};
            float2 o1 = {a.z + bv.x, a.w + bv.y};
            if (GLOB) {
                float2 gv = *(const float2*)&gw[c];
                o0.x += cc0 * gv.x; o0.y += cc0 * gv.y;
                o1.x += cc1 * gv.x; o1.y += cc1 * gv.y;
            }
            if (RELU) {
                o0.x = fmaxf(o0.x, 0.f); o0.y = fmaxf(o0.y, 0.f);
                o1.x = fmaxf(o1.x, 0.f); o1.y = fmaxf(o1.y, 0.f);
            }
            if (!ZOUT) {
                *(float2*)&Y[(size_t)r0 * 128 + c] = o0;
                *(float2*)&Y[(size_t)r1 * 128 + c] = o1;
            }
            if (MAXP) {
                colmax[f][0] = fmaxf(colmax[f][0], fmaxf(o0.x, o1.x));
                colmax[f][1] = fmaxf(colmax[f][1], fmaxf(o0.y, o1.y));
            }
            if (ZOUT) {
                float w3a = W3[c], w3b = W3[c + 1];
                zp[mf][0] += o0.x * w3a + o0.y * w3b;
                zp[mf][1] += o1.x * w3a + o1.y * w3b;
            }
        }
    }

    if (MAXP) {
        #pragma unroll
        for (int f = 0; f < 8; f++) {
            int c = n0 + f * 8 + 2 * tg;
            atomicMax(&smax[c],     __float_as_int(colmax[f][0]));
            atomicMax(&smax[c + 1], __float_as_int(colmax[f][1]));
        }
        __syncthreads();
        if (tid < 128) g_mpp[(size_t)blockIdx.x * HID + tid] = __int_as_float(smax[tid]);
    }

    if (ZOUT) {
        int slot = ((wid >> 2) << 2) | tg;
        #pragma unroll
        for (int mf = 0; mf < 2; mf++) {
            szp[m0 + mf * 16 + gp][slot]     = zp[mf][0];
            szp[m0 + mf * 16 + gp + 8][slot] = zp[mf][1];
        }
        __syncthreads();
        if (tid < 128) {
            float z = 0.f;
            #pragma unroll
            for (int k = 0; k < 8; k++) z += szp[tid][k];
            g_z[rbase + tid] = z;
        }
    }
}

// ---------------- fused maxpool stage-2 + global path matmuls ----------------
__global__ void k_globs2(const float* __restrict__ Wf, const float* __restrict__ bf,
                         const float* __restrict__ W2) {
    __shared__ float s1[HID];
    __shared__ float s2[HID];
    int g = blockIdx.x, t = threadIdx.x;
    float m = -CUDART_INF_F;
    #pragma unroll
    for (int s = 0; s < 8; s++) m = fmaxf(m, g_mpp[(g * 8 + s) * HID + t]);
    s1[t] = m;
    __syncthreads();
    float acc = bf[t];
    for (int k = 0; k < HID; k++) acc += s1[k] * Wf[k * HID + t];
    s2[t] = acc;
    __syncthreads();
    float a2 = 0.f;
    for (int k = 0; k < HID; k++) a2 += s2[k] * W2[(HID + k) * HID + t];
    g_gW[g * HID + t] = a2;
}

// ---------------- fused logit + per-graph top-K mask ----------------
// z staged in smem; src indices masked to graph-local (edges are intra-graph).
__global__ __launch_bounds__(256) void k_logitk(const float* __restrict__ b3,
                                                float* __restrict__ out) {
    __shared__ float sz[NPER];
    __shared__ float slog[NPER];
    __shared__ float v[NPER];
    __shared__ float wmax[8];
    __shared__ float sth;
    __shared__ int sidx;
    const int g = blockIdx.x, t = threadIdx.x;
    const int lane = t & 31, warp = t >> 5;
    const float bb = b3[0];

    for (int i = t; i < NPER; i += 256) sz[i] = g_z[g * NPER + i];
    __syncthreads();

    for (int ln = warp; ln < NPER; ln += 8) {
        int node = g * NPER + ln;
        int jb = g_off[node], dg = g_deg[node];
        float part = 0.f;
        for (int j = lane; j < dg; j += 32) {
            float2 e = g_csre[jb + j];
            part += e.y * sz[__float_as_int(e.x) & (NPER - 1)];
        }
        #pragma unroll
        for (int o = 16; o; o >>= 1) part += __shfl_xor_sync(0xffffffffu, part, o);
        if (lane == 0) {
            float dv = g_dinv[node];
            float lv = part + dv * dv * sz[ln] + bb;
            slog[ln] = lv;
            v[ln] = lv;
        }
    }
    __syncthreads();

    for (int it = 0; it < TOPK; it++) {
        float m = -CUDART_INF_F;
        for (int i = t; i < NPER; i += 256) m = fmaxf(m, v[i]);
        #pragma unroll
        for (int o = 16; o; o >>= 1) m = fmaxf(m, __shfl_xor_sync(0xffffffffu, m, o));
        if (lane == 0) wmax[warp] = m;
        __syncthreads();
        if (t == 0) {
            float mm = wmax[0];
            #pragma unroll
            for (int w = 1; w < 8; w++) mm = fmaxf(mm, wmax[w]);
            sth = mm;
            sidx = 0x7fffffff;
        }
        __syncthreads();
        float mm = sth;
        for (int i = t; i < NPER; i += 256)
            if (v[i] == mm) atomicMin(&sidx, i);
        __syncthreads();
        if (t == 0) v[sidx] = -CUDART_INF_F;
        __syncthreads();
    }
    float th = sth;
    for (int i = t; i < NPER; i += 256)
        out[g * NPER + i] = (slog[i] >= th) ? 1.0f : 0.0f;
}

// ---------------- host launcher ----------------
extern "C" void kernel_launch(void* const* d_in, const int* in_sizes, int n_in,
                              void* d_out, int out_size) {
    const float* x    = (const float*)d_in[0];
    const int*   esrc = (const int*)d_in[1];
    const int*   edst = (const int*)d_in[2];
    const float* W0 = (const float*)d_in[4];
    const float* b0 = (const float*)d_in[5];
    const float* W1 = (const float*)d_in[6];
    const float* b1 = (const float*)d_in[7];
    const float* Wf = (const float*)d_in[8];
    const float* bf = (const float*)d_in[9];
    const float* W2 = (const float*)d_in[10];
    const float* b2 = (const float*)d_in[11];
    const float* W3 = (const float*)d_in[12];
    const float* b3 = (const float*)d_in[13];
    float* out = (float*)d_out;

    float *T0, *T1;
    int* degp;
    cudaGetSymbolAddress((void**)&T0, g_T0);
    cudaGetSymbolAddress((void**)&T1, g_T1);
    cudaGetSymbolAddress((void**)&degp, g_deg);

    const int SM64  = (128 * 68  + 2 * 64  * 136) * 4;   // 104448
    const int SM128 = (128 * 132 + 2 * 128 * 136) * 4;   // 206848
    cudaFuncSetAttribute(k_mgemm<64, true, false, true, false>,
                         cudaFuncAttributeMaxDynamicSharedMemorySize, SM64);
    cudaFuncSetAttribute(k_mgemm<128, true, false, false, false>,
                         cudaFuncAttributeMaxDynamicSharedMemorySize, SM128);
    cudaFuncSetAttribute(k_mgemm<128, true, true, false, true>,
                         cudaFuncAttributeMaxDynamicSharedMemorySize, SM128);

    // --- CSR + norms (hist -> fused per-graph scan -> fill) ---
    cudaMemsetAsync(degp, 0, NNODES * sizeof(int));
    k_hist<<<NEDGES / 256, 256>>>(edst);
    k_scan<<<NGRAPH, 1024>>>();
    k_fill<<<NEDGES / 256, 256>>>(esrc, edst);

    // --- conv0: h0 = relu(agg(x) @ W0 + b0); epilogue emits maxpool partials ---
    k_agg64<true><<<NNODES / 8, 256>>>(x, T1);
    k_mgemm<64, true, false, true, false><<<NNODES / 128, 256, SM64>>>(T1, W0, b0, T0, nullptr);

    // --- global path: mp2 + (mp @ Wf + bf) @ W2_bottom ---
    k_globs2<<<NGRAPH, HID>>>(Wf, bf, W2);

    // --- conv1 (applied twice with same weights) ---
    k_agg128<<<NNODES / 8, 256>>>(T0, T1);
    k_mgemm<128, true, false, false, false><<<NNODES / 128, 256, SM128>>>(T1, W1, b1, T0, nullptr);
    k_agg128<<<NNODES / 8, 256>>>(T0, T1);
    k_mgemm<128, true, false, false, false><<<NNODES / 128, 256, SM128>>>(T1, W1, b1, T0, nullptr);

    // --- conv2 + conv3 projection fused: epilogue computes z = h . W3, no h store ---
    k_agg128<<<NNODES / 8, 256>>>(T0, T1);
    k_mgemm<128, true, true, false, true><<<NNODES / 128, 256, SM128>>>(T1, W2, b2, nullptr, W3);

    // --- fused logit + per-graph top-10 mask ---
    k_logitk<<<NGRAPH, 256>>>(b3, out);
}